// round 11
// baseline (speedup 1.0000x reference)
#include <cuda_runtime.h>
#include <cuda_fp16.h>

// LightGCN 3-layer propagation, N=200000, E=3.2M, D=64+64.
// R10: split the feature dim into two 64-col halves (int | geo) processed
// sequentially so each pass's gather working set (~51MB fp16 + 13MB CSR)
// is firmly L2-resident, and each edge-gather is exactly one 128B line
// (64 x fp16, one LDG.32 per lane). Kept: pre-scaled fp16 rows (pure-sum
// gather), src-only 4B CSR, fused epilogue, default cache policy.
// NOTE: __device__ globals referenced ONLY from device code.

#define USER_NUM 100000
#define N_NODES  200000
#define NE       3200000

__device__ int   g_cnt[N_NODES];
__device__ int   g_rowptr[N_NODES + 1];
__device__ float g_dis[N_NODES];        // deg>0 ? rsqrt(deg) : 0
__device__ float g_sqd[N_NODES];        // deg>0 ? sqrt(deg)  : 0
__device__ int   g_csr_src[NE];
// 6 half-buffers: (layer 0..2) x (half 0..1), each N x 32 uints (64 fp16).
__device__ unsigned g_sb[(size_t)6 * N_NODES * 32];

__device__ __forceinline__ unsigned* sbuf(int layer, int half) {
    return g_sb + (size_t)(layer * 2 + half) * ((size_t)N_NODES * 32);
}

// ---- fp16 pair <-> float2 -------------------------------------------------
__device__ __forceinline__ unsigned f2_to_h(float2 v) {
    __half2 h = __floats2half2_rn(v.x, v.y);
    return *reinterpret_cast<unsigned*>(&h);
}
__device__ __forceinline__ float2 h_to_f2(unsigned u) {
    __half2 h = *reinterpret_cast<__half2*>(&u);
    return __half22float2(h);
}

// ---------------------------------------------------------------------------
__global__ void k_zero() {
    int i = blockIdx.x * blockDim.x + threadIdx.x;
    int stride = gridDim.x * blockDim.x;
    for (; i < N_NODES; i += stride) g_cnt[i] = 0;
}

__global__ void k_count(const int* __restrict__ dst) {
    int i = blockIdx.x * blockDim.x + threadIdx.x;
    int stride = gridDim.x * blockDim.x;
    for (; i < NE; i += stride) {
        atomicAdd(&g_cnt[dst[i]], 1);
    }
}

// Single-block exclusive scan over g_cnt -> g_rowptr; computes dis & sqd.
// Resets g_cnt to 0 so k_scatter can reuse it as the insertion cursor.
__global__ void k_scan() {
    __shared__ int sums[1024];
    const int t = threadIdx.x;
    const int CH = (N_NODES + 1023) / 1024;   // 196
    int beg = t * CH;
    int end = beg + CH; if (end > N_NODES) end = N_NODES;

    int s = 0;
    for (int i = beg; i < end; i++) {
        int c = g_cnt[i];
        s += c;
        float fc = (float)c;
        g_dis[i] = (c > 0) ? rsqrtf(fc) : 0.0f;
        g_sqd[i] = (c > 0) ? sqrtf(fc)  : 0.0f;
    }
    sums[t] = s;
    __syncthreads();

    for (int off = 1; off < 1024; off <<= 1) {
        int v = 0;
        if (t >= off) v = sums[t - off];
        __syncthreads();
        sums[t] += v;
        __syncthreads();
    }

    int run = (t == 0) ? 0 : sums[t - 1];
    for (int i = beg; i < end; i++) {
        g_rowptr[i] = run;
        run += g_cnt[i];
        g_cnt[i] = 0;                 // becomes the scatter cursor
    }
    if (t == 1023) g_rowptr[N_NODES] = run;
}

// CSR scatter: src index only (4B).
__global__ void k_scatter(const int* __restrict__ src, const int* __restrict__ dst) {
    int i = blockIdx.x * blockDim.x + threadIdx.x;
    int stride = gridDim.x * blockDim.x;
    for (; i < NE; i += stride) {
        int s = src[i];
        int d = dst[i];
        int pos = g_rowptr[d] + atomicAdd(&g_cnt[d], 1);
        g_csr_src[pos] = s;
    }
}

// Per-lane float2 of a 64-col half row, from the original fp32 inputs.
__device__ __forceinline__ float2 load_half_f2(
    const float2* __restrict__ ua, const float2* __restrict__ ia,
    int node, int lane)
{
    return (node < USER_NUM) ? ua[node * 32 + lane]
                             : ia[(node - USER_NUM) * 32 + lane];
}

// Pack both halves' s0 = dis * x0 (fp16).
__global__ void k_pack(const float2* __restrict__ ui, const float2* __restrict__ ii,
                       const float2* __restrict__ ug, const float2* __restrict__ ig) {
    int idx = blockIdx.x * blockDim.x + threadIdx.x;
    int stride = gridDim.x * blockDim.x;
    const int total = N_NODES * 32;
    unsigned* s0i = sbuf(0, 0);
    unsigned* s0g = sbuf(0, 1);
    for (; idx < total; idx += stride) {
        int node = idx >> 5;
        int lane = idx & 31;
        float w = __ldg(&g_dis[node]);
        float2 a = load_half_f2(ui, ii, node, lane);
        float2 b = load_half_f2(ug, ig, node, lane);
        a.x *= w; a.y *= w;
        b.x *= w; b.y *= w;
        s0i[idx] = f2_to_h(a);
        s0g[idx] = f2_to_h(b);
    }
}

// Pure-sum gather over pre-scaled fp16 half-rows (one 128B line per edge).
__device__ __forceinline__ float2 gather_node(const unsigned* __restrict__ xin,
                                              int node, int lane) {
    int beg = __ldg(&g_rowptr[node]);
    int end = __ldg(&g_rowptr[node + 1]);
    float ax = 0.f, ay = 0.f;
    int i = beg;
    for (; i + 8 <= end; i += 8) {
        int s0 = __ldg(&g_csr_src[i + 0]);
        int s1 = __ldg(&g_csr_src[i + 1]);
        int s2 = __ldg(&g_csr_src[i + 2]);
        int s3 = __ldg(&g_csr_src[i + 3]);
        int s4 = __ldg(&g_csr_src[i + 4]);
        int s5 = __ldg(&g_csr_src[i + 5]);
        int s6 = __ldg(&g_csr_src[i + 6]);
        int s7 = __ldg(&g_csr_src[i + 7]);
        unsigned u0 = __ldg(&xin[s0 * 32 + lane]);
        unsigned u1 = __ldg(&xin[s1 * 32 + lane]);
        unsigned u2 = __ldg(&xin[s2 * 32 + lane]);
        unsigned u3 = __ldg(&xin[s3 * 32 + lane]);
        unsigned u4 = __ldg(&xin[s4 * 32 + lane]);
        unsigned u5 = __ldg(&xin[s5 * 32 + lane]);
        unsigned u6 = __ldg(&xin[s6 * 32 + lane]);
        unsigned u7 = __ldg(&xin[s7 * 32 + lane]);
        float2 v0 = h_to_f2(u0), v1 = h_to_f2(u1);
        float2 v2 = h_to_f2(u2), v3 = h_to_f2(u3);
        float2 v4 = h_to_f2(u4), v5 = h_to_f2(u5);
        float2 v6 = h_to_f2(u6), v7 = h_to_f2(u7);
        ax += v0.x + v1.x + v2.x + v3.x + v4.x + v5.x + v6.x + v7.x;
        ay += v0.y + v1.y + v2.y + v3.y + v4.y + v5.y + v6.y + v7.y;
    }
    for (; i < end; ++i) {
        int s = __ldg(&g_csr_src[i]);
        float2 v = h_to_f2(__ldg(&xin[s * 32 + lane]));
        ax += v.x; ay += v.y;
    }
    return make_float2(ax, ay);
}

// Layers 1 & 2 (per half): s_L[d] = dis[d]^2 * sum. Buffers device-selected.
__global__ void __launch_bounds__(256) k_prop12(int layer, int half) {
    int gtid = blockIdx.x * blockDim.x + threadIdx.x;
    int node = gtid >> 5;
    if (node >= N_NODES) return;
    int lane = threadIdx.x & 31;

    const unsigned* xin  = sbuf(layer - 1, half);
    unsigned*       xout = sbuf(layer, half);

    float2 a = gather_node(xin, node, lane);
    float d  = __ldg(&g_dis[node]);
    float d2 = d * d;
    a.x *= d2; a.y *= d2;
    xout[node * 32 + lane] = f2_to_h(a);
}

// Layer 3 (per half) fused with final reduction:
// out = (x0 + (s1+s2)*sqd + dis*gather(s2)) / 16
__global__ void __launch_bounds__(256) k_prop3(
    const float2* __restrict__ ui, const float2* __restrict__ ii,
    const float2* __restrict__ ug, const float2* __restrict__ ig,
    float2* __restrict__ out, int half)
{
    int gtid = blockIdx.x * blockDim.x + threadIdx.x;
    int node = gtid >> 5;
    if (node >= N_NODES) return;
    int lane = threadIdx.x & 31;

    const unsigned* s1p = sbuf(1, half);
    const unsigned* s2p = sbuf(2, half);
    const float2* ua = half ? ug : ui;
    const float2* ia = half ? ig : ii;

    float2 a = gather_node(s2p, node, lane);             // Σ s2[src]

    float dis = __ldg(&g_dis[node]);
    float sqd = __ldg(&g_sqd[node]);

    float2 base = load_half_f2(ua, ia, node, lane);      // x0 (fp32)
    float2 v1 = h_to_f2(__ldg(&s1p[node * 32 + lane]));
    float2 v2 = h_to_f2(__ldg(&s2p[node * 32 + lane]));

    const float s = 1.0f / 16.0f;
    float2 r;
    r.x = (base.x + (v1.x + v2.x) * sqd + a.x * dis) * s;
    r.y = (base.y + (v1.y + v2.y) * sqd + a.y * dis) * s;

    // out layout: [int section N*64 | geo section N*64] as float2 granules
    out[(size_t)half * N_NODES * 32 + node * 32 + lane] = r;
}

// ---------------------------------------------------------------------------
extern "C" void kernel_launch(void* const* d_in, const int* in_sizes, int n_in,
                              void* d_out, int out_size) {
    const float2* user_int = (const float2*)d_in[0];
    const float2* item_int = (const float2*)d_in[1];
    const float2* user_geo = (const float2*)d_in[2];
    const float2* item_geo = (const float2*)d_in[3];
    const int*    edge     = (const int*)d_in[4];
    const int* src = edge;        // row 0 of [2, E]
    const int* dst = edge + NE;   // row 1

    float2* out = (float2*)d_out;

    const int TB = 256;
    const int prop_blocks = (N_NODES * 32 + TB - 1) / TB;   // 25000

    k_zero<<<512, TB>>>();
    k_count<<<4096, TB>>>(dst);
    k_scan<<<1, 1024>>>();
    k_scatter<<<4096, TB>>>(src, dst);
    k_pack<<<prop_blocks, TB>>>(user_int, item_int, user_geo, item_geo);

    for (int half = 0; half < 2; ++half) {
        k_prop12<<<prop_blocks, TB>>>(1, half);   // s0 -> s1
        k_prop12<<<prop_blocks, TB>>>(2, half);   // s1 -> s2
        k_prop3<<<prop_blocks, TB>>>(user_int, item_int, user_geo, item_geo,
                                     out, half);
    }
}

// round 13
// speedup vs baseline: 1.4560x; 1.4560x over previous
#include <cuda_runtime.h>
#include <cuda_fp16.h>

// LightGCN 3-layer propagation, N=200000, E=3.2M, D=64+64 fused to 128.
// R13 = R4 VERBATIM resubmit (R12 was a container infra failure; the A/B
// experiment never ran). Purpose: resolve the container-clock confound —
// R4 measured 768us but every later (lower-traffic!) variant measured
// ~1000us on different containers. If this returns ~768 the R4 design is
// genuinely better; if ~1000, the 768 was container variance.
// Design: CSR-by-dst per launch, warp-per-node gather, fp16 rows (256B),
// int2(src, norm-bits) CSR, fp32 accumulation, fused final reduction.
// NOTE: __device__ globals referenced ONLY from device code.

#define USER_NUM 100000
#define N_NODES  200000
#define NE       3200000

__device__ int   g_cnt[N_NODES];
__device__ int   g_cursor[N_NODES];
__device__ int   g_rowptr[N_NODES + 1];
__device__ float g_dis[N_NODES];
__device__ int2  g_csr[NE];                        // (src, norm-bits)
__device__ uint2 g_e0h[(size_t)N_NODES * 32];      // fp16 rows, 256B each
__device__ uint2 g_e1h[(size_t)N_NODES * 32];
__device__ uint2 g_e2h[(size_t)N_NODES * 32];

// ---- fp16 <-> fp32 row-chunk helpers (4 floats <-> uint2) ------------------
__device__ __forceinline__ uint2 f4_to_h(float4 v) {
    __half2 lo = __floats2half2_rn(v.x, v.y);
    __half2 hi = __floats2half2_rn(v.z, v.w);
    uint2 u;
    u.x = *reinterpret_cast<unsigned*>(&lo);
    u.y = *reinterpret_cast<unsigned*>(&hi);
    return u;
}
__device__ __forceinline__ float4 h_to_f4(uint2 u) {
    __half2 lo = *reinterpret_cast<__half2*>(&u.x);
    __half2 hi = *reinterpret_cast<__half2*>(&u.y);
    float2 a = __half22float2(lo);
    float2 b = __half22float2(hi);
    return make_float4(a.x, a.y, b.x, b.y);
}

// ---------------------------------------------------------------------------
__global__ void k_zero() {
    int i = blockIdx.x * blockDim.x + threadIdx.x;
    int stride = gridDim.x * blockDim.x;
    for (; i < N_NODES; i += stride) {
        g_cnt[i] = 0;
        g_cursor[i] = 0;
    }
}

__global__ void k_count(const int* __restrict__ dst) {
    int i = blockIdx.x * blockDim.x + threadIdx.x;
    int stride = gridDim.x * blockDim.x;
    for (; i < NE; i += stride) {
        atomicAdd(&g_cnt[dst[i]], 1);
    }
}

// Single-block exclusive scan over g_cnt -> g_rowptr; also computes g_dis.
__global__ void k_scan() {
    __shared__ int sums[1024];
    const int t = threadIdx.x;
    const int CH = (N_NODES + 1023) / 1024;   // 196
    int beg = t * CH;
    int end = beg + CH; if (end > N_NODES) end = N_NODES;

    int s = 0;
    for (int i = beg; i < end; i++) {
        int c = g_cnt[i];
        s += c;
        g_dis[i] = (c > 0) ? rsqrtf((float)c) : 0.0f;
    }
    sums[t] = s;
    __syncthreads();

    for (int off = 1; off < 1024; off <<= 1) {
        int v = 0;
        if (t >= off) v = sums[t - off];
        __syncthreads();
        sums[t] += v;
        __syncthreads();
    }

    int run = (t == 0) ? 0 : sums[t - 1];
    for (int i = beg; i < end; i++) {
        g_rowptr[i] = run;
        run += g_cnt[i];
    }
    if (t == 1023) g_rowptr[N_NODES] = run;
}

__global__ void k_scatter(const int* __restrict__ src, const int* __restrict__ dst) {
    int i = blockIdx.x * blockDim.x + threadIdx.x;
    int stride = gridDim.x * blockDim.x;
    for (; i < NE; i += stride) {
        int s = src[i];
        int d = dst[i];
        int pos = g_rowptr[d] + atomicAdd(&g_cursor[d], 1);
        float w = g_dis[s] * g_dis[d];
        g_csr[pos] = make_int2(s, __float_as_int(w));
    }
}

// Per-lane float4 chunk of the fused 128-col row, from the original inputs.
__device__ __forceinline__ float4 load_input_chunk(
    const float4* __restrict__ ui, const float4* __restrict__ ii,
    const float4* __restrict__ ug, const float4* __restrict__ ig,
    int node, int lane)
{
    if (lane < 16) {
        return (node < USER_NUM) ? ui[node * 16 + lane]
                                 : ii[(node - USER_NUM) * 16 + lane];
    } else {
        int q = lane - 16;
        return (node < USER_NUM) ? ug[node * 16 + q]
                                 : ig[(node - USER_NUM) * 16 + q];
    }
}

// Pack inputs into fused fp16 rows (e0h).
__global__ void k_pack(const float4* __restrict__ ui, const float4* __restrict__ ii,
                       const float4* __restrict__ ug, const float4* __restrict__ ig) {
    int idx = blockIdx.x * blockDim.x + threadIdx.x;
    int stride = gridDim.x * blockDim.x;
    const int total = N_NODES * 32;
    for (; idx < total; idx += stride) {
        int node = idx >> 5;
        int lane = idx & 31;
        g_e0h[idx] = f4_to_h(load_input_chunk(ui, ii, ug, ig, node, lane));
    }
}

// Shared gather core: fp32 accumulation over fp16 rows.
__device__ __forceinline__ float4 gather_node(const uint2* __restrict__ xin,
                                              int node, int lane) {
    int beg = __ldg(&g_rowptr[node]);
    int end = __ldg(&g_rowptr[node + 1]);
    float4 a = make_float4(0.f, 0.f, 0.f, 0.f);
    int i = beg;
    for (; i + 4 <= end; i += 4) {
        int2 e0 = __ldg(&g_csr[i + 0]);
        int2 e1 = __ldg(&g_csr[i + 1]);
        int2 e2 = __ldg(&g_csr[i + 2]);
        int2 e3 = __ldg(&g_csr[i + 3]);
        uint2 u0 = __ldg(&xin[e0.x * 32 + lane]);
        uint2 u1 = __ldg(&xin[e1.x * 32 + lane]);
        uint2 u2 = __ldg(&xin[e2.x * 32 + lane]);
        uint2 u3 = __ldg(&xin[e3.x * 32 + lane]);
        float w0 = __int_as_float(e0.y), w1 = __int_as_float(e1.y);
        float w2 = __int_as_float(e2.y), w3 = __int_as_float(e3.y);
        float4 v0 = h_to_f4(u0), v1 = h_to_f4(u1);
        float4 v2 = h_to_f4(u2), v3 = h_to_f4(u3);
        a.x += w0 * v0.x + w1 * v1.x + w2 * v2.x + w3 * v3.x;
        a.y += w0 * v0.y + w1 * v1.y + w2 * v2.y + w3 * v3.y;
        a.z += w0 * v0.z + w1 * v1.z + w2 * v2.z + w3 * v3.z;
        a.w += w0 * v0.w + w1 * v1.w + w2 * v2.w + w3 * v3.w;
    }
    for (; i < end; ++i) {
        int2 e = __ldg(&g_csr[i]);
        float w = __int_as_float(e.y);
        float4 v = h_to_f4(__ldg(&xin[e.x * 32 + lane]));
        a.x += w * v.x; a.y += w * v.y; a.z += w * v.z; a.w += w * v.w;
    }
    return a;
}

// Layers 1 & 2: gather -> write fp16. Buffers selected in DEVICE code.
// layer==1: e0h -> e1h ; layer==2: e1h -> e2h
__global__ void __launch_bounds__(256) k_prop12(int layer) {
    int gtid = blockIdx.x * blockDim.x + threadIdx.x;
    int node = gtid >> 5;
    if (node >= N_NODES) return;
    int lane = threadIdx.x & 31;

    const uint2* xin  = (layer == 1) ? g_e0h : g_e1h;
    uint2*       xout = (layer == 1) ? g_e1h : g_e2h;

    float4 a = gather_node(xin, node, lane);
    xout[node * 32 + lane] = f4_to_h(a);
}

// Layer 3 fused with final reduction:
// out = (e0_fp32 + e1 + e2 + conv(e2)) / 16, split into [int | geo] sections.
__global__ void __launch_bounds__(256) k_prop3(
    const float4* __restrict__ ui, const float4* __restrict__ ii,
    const float4* __restrict__ ug, const float4* __restrict__ ig,
    float4* __restrict__ out)
{
    int gtid = blockIdx.x * blockDim.x + threadIdx.x;
    int node = gtid >> 5;
    if (node >= N_NODES) return;
    int lane = threadIdx.x & 31;

    float4 a = gather_node(g_e2h, node, lane);           // layer-3 output

    float4 base = load_input_chunk(ui, ii, ug, ig, node, lane);  // e0 (fp32)
    float4 v1 = h_to_f4(__ldg(&g_e1h[node * 32 + lane]));
    float4 v2 = h_to_f4(__ldg(&g_e2h[node * 32 + lane]));

    const float s = 1.0f / 16.0f;
    float4 r;
    r.x = (base.x + v1.x + v2.x + a.x) * s;
    r.y = (base.y + v1.y + v2.y + a.y) * s;
    r.z = (base.z + v1.z + v2.z + a.z) * s;
    r.w = (base.w + v1.w + v2.w + a.w) * s;

    const int geo_base = N_NODES * 16;
    if (lane < 16) out[node * 16 + lane] = r;
    else           out[geo_base + node * 16 + (lane - 16)] = r;
}

// ---------------------------------------------------------------------------
extern "C" void kernel_launch(void* const* d_in, const int* in_sizes, int n_in,
                              void* d_out, int out_size) {
    const float4* user_int = (const float4*)d_in[0];
    const float4* item_int = (const float4*)d_in[1];
    const float4* user_geo = (const float4*)d_in[2];
    const float4* item_geo = (const float4*)d_in[3];
    const int*    edge     = (const int*)d_in[4];
    const int* src = edge;        // row 0 of [2, E]
    const int* dst = edge + NE;   // row 1

    float4* out = (float4*)d_out;

    const int TB = 256;
    const int prop_blocks = (N_NODES * 32 + TB - 1) / TB;   // 25000

    k_zero<<<512, TB>>>();
    k_count<<<4096, TB>>>(dst);
    k_scan<<<1, 1024>>>();
    k_scatter<<<4096, TB>>>(src, dst);
    k_pack<<<prop_blocks, TB>>>(user_int, item_int, user_geo, item_geo);

    k_prop12<<<prop_blocks, TB>>>(1);   // layer 1: e0h -> e1h
    k_prop12<<<prop_blocks, TB>>>(2);   // layer 2: e1h -> e2h
    k_prop3<<<prop_blocks, TB>>>(user_int, item_int, user_geo, item_geo, out);
}